// round 14
// baseline (speedup 1.0000x reference)
#include <cuda_runtime.h>
#include <math.h>

#define BATCH  64
#define TSEQ   3136
#define NTOK   (BATCH*TSEQ)
#define INDIM  147
#define DIM    64
#define MF     32
#define NW     16
#define NTILE  196            // TSEQ/16
#define NTILEG (NTOK/16)      // 12544

#define CW     68             // padded weight row stride (floats)

__device__ float d_v [NTOK*DIM];      // [token][64]
__device__ float d_kp[NTOK*MF];       // [token][32]
__device__ float d_qp[NTOK*MF];       // tiled [tile][m][16]
__device__ float d_kpsum[BATCH*MF];
__device__ float d_kptv [BATCH*DIM*MF];

typedef unsigned long long u64t;

__device__ __forceinline__ u64t dup2(float a) {
    u64t r; asm("mov.b64 %0, {%1, %1};" : "=l"(r) : "f"(a)); return r;
}
__device__ __forceinline__ u64t pack2(float lo, float hi) {
    u64t r; asm("mov.b64 %0, {%1, %2};" : "=l"(r) : "f"(lo), "f"(hi)); return r;
}
__device__ __forceinline__ void up2(u64t v, float& a, float& b) {
    asm("mov.b64 {%0, %1}, %2;" : "=f"(a), "=f"(b) : "l"(v));
}
__device__ __forceinline__ u64t ffma2(u64t a, u64t b, u64t c) {
    u64t r; asm("fma.rn.f32x2 %0, %1, %2, %3;" : "=l"(r) : "l"(a), "l"(b), "l"(c));
    return r;
}
__device__ __forceinline__ u64t mul2(u64t a, u64t b) {
    u64t r; asm("mul.rn.f32x2 %0, %1, %2;" : "=l"(r) : "l"(a), "l"(b)); return r;
}
__device__ __forceinline__ u64t add2(u64t a, u64t b) {
    u64t r; asm("add.rn.f32x2 %0, %1, %2;" : "=l"(r) : "l"(a), "l"(b)); return r;
}
__device__ __forceinline__ u64t shflx(u64t v, int m) {
    return __shfl_xor_sync(0xffffffffu, v, m);
}
__device__ __forceinline__ float gelu(float z) {
    return 0.5f*z*(1.0f + erff(z*0.70710678118654752f));
}

// ---- shared register-tile helpers (8 cols x 4 tokens per lane) ----
__device__ __forceinline__ void gstep(const float* ap, const float* wp, u64t acc[8][2]) {
    ulonglong2 av = *(const ulonglong2*)ap;
    float4 w0 = *(const float4*)wp;
    float4 w1 = *(const float4*)(wp + 4);
#pragma unroll
    for (int f = 0; f < 4; f++) {
        u64t wd = dup2(((const float*)&w0)[f]);
        acc[f][0] = ffma2(wd, av.x, acc[f][0]);
        acc[f][1] = ffma2(wd, av.y, acc[f][1]);
    }
#pragma unroll
    for (int f = 0; f < 4; f++) {
        u64t wd = dup2(((const float*)&w1)[f]);
        acc[4+f][0] = ffma2(wd, av.x, acc[4+f][0]);
        acc[4+f][1] = ffma2(wd, av.y, acc[4+f][1]);
    }
}
// ACT tile [64][16] with kg-swizzle; wbase already includes lane's wc offset.
__device__ __forceinline__ void gemm64(const float* ACTw, int r, const float* wbase, u64t acc[8][2]) {
#pragma unroll 2
    for (int kg = 0; kg < 8; kg++) {
        const float* ap = ACTw + kg*128 + 4*(r ^ (kg & 3));
        const float* wp = wbase + kg*8*CW;
#pragma unroll
        for (int kk = 0; kk < 8; kk++)
            gstep(ap + kk*16, wp + kk*CW, acc);
    }
}
__device__ __forceinline__ void sts8(float* ACTw, int c, int r, u64t v[8][2]) {
    int sw = 4*(r ^ (c & 3));
#pragma unroll
    for (int f = 0; f < 8; f++)
        *(ulonglong2*)(ACTw + (8*c+f)*16 + sw) = make_ulonglong2(v[f][0], v[f][1]);
}
__device__ __forceinline__ void bias8(const float* base, int wc, u64t a[8][2]) {
    float4 b0 = *(const float4*)(base + wc), b1 = *(const float4*)(base + wc + 4);
#pragma unroll
    for (int f = 0; f < 4; f++) { u64t d = dup2(((const float*)&b0)[f]); a[f][0]=d; a[f][1]=d; }
#pragma unroll
    for (int f = 0; f < 4; f++) { u64t d = dup2(((const float*)&b1)[f]); a[4+f][0]=d; a[4+f][1]=d; }
}

// ===================== Kernel A v2 (register tiles, 16-token tiles, 256 thr) =====================
#define ANW    8
#define A2_W1   0                        // 148*68 = 10064 (row 147 zeroed)
#define A2_WK   10064                    // 3 * 64*68 = 13056
#define A2_WT   23120                    // w^T [d][m]: 64*36 = 2304
#define A2_BIAS 25424                    // 6*68: b1,g1,be1,bk,bq,bv
#define A2_SX   25832                    // per warp 148*16 = 2368
#define A2_ACT  (A2_SX + ANW*2368)      // per warp 64*16 = 1024
#define A2_SMEM_BYTES ((A2_ACT + ANW*1024)*4)   // 211872

__global__ void __launch_bounds__(256) kernelA(
    const float* __restrict__ x,  const float* __restrict__ W1, const float* __restrict__ b1,
    const float* __restrict__ Wk, const float* __restrict__ bk,
    const float* __restrict__ g1, const float* __restrict__ be1,
    const float* __restrict__ wrf)
{
    extern __shared__ float sm[];
    const int tid = threadIdx.x, lane = tid & 31, warp = tid >> 5;

    for (int idx = tid; idx < INDIM*64; idx += 256) {
        int i = idx >> 6, j = idx & 63;
        sm[A2_W1 + i*CW + j + 4*(j >> 5)] = W1[idx];
    }
    if (tid < CW) sm[A2_W1 + 147*CW + tid] = 0.f;
    for (int idx = tid; idx < 64*192; idx += 256) {
        int ki = idx / 192, j = idx - ki*192;
        int part = j >> 6, jj = j & 63;
        sm[A2_WK + part*(64*CW) + ki*CW + jj + 4*(jj >> 5)] = Wk[idx];
    }
    for (int idx = tid; idx < MF*DIM; idx += 256) {
        int m = idx >> 6, d = idx & 63;
        sm[A2_WT + d*36 + m] = wrf[idx];
    }
    if (tid < 64) {
        int pos = tid + 4*(tid >> 5);
        sm[A2_BIAS + 0*CW + pos] = b1 [tid];
        sm[A2_BIAS + 1*CW + pos] = g1 [tid];
        sm[A2_BIAS + 2*CW + pos] = be1[tid];
        sm[A2_BIAS + 3*CW + pos] = bk [tid];
        sm[A2_BIAS + 4*CW + pos] = bk [64 + tid];
        sm[A2_BIAS + 5*CW + pos] = bk [128 + tid];
    }
    __syncthreads();

    const int c = lane & 7, r = lane >> 3;
    const int wc = 8*c + 4*(c >> 2);
    const int tb4 = 4*r;
    const int tl = lane >> 2, il = lane & 3;
    float* SXTw  = sm + A2_SX  + warp*2368;
    float* ACTw  = sm + A2_ACT + warp*1024;
    float* KACTw = SXTw;   // reuse: x data dead after GEMM1
    const float inv64 = 1.0f/64.0f;
    const float rsM   = 0.17677669529663689f;

    for (int tile = blockIdx.x*ANW + warp; tile < NTILEG; tile += gridDim.x*ANW) {
        const long long tok0 = (long long)tile * 16;
        __syncwarp();
        // ---- load x transposed [i][16] ----
#pragma unroll
        for (int h = 0; h < 2; h++) {
            const float* xr = x + (tok0 + 8*h + tl)*INDIM;
            const int tcol = 8*h + tl;
#pragma unroll
            for (int it = 0; it < 10; it++) {
                int i4 = il + 4*it;
                if (i4 <= 36) {
                    int i0 = 4*i4;
                    float v0 = xr[i0], v1 = xr[i0+1], v2 = xr[i0+2];
                    float v3 = (i0+3 < INDIM) ? xr[i0+3] : 0.f;
                    SXTw[(i0  )*16 + tcol] = v0; SXTw[(i0+1)*16 + tcol] = v1;
                    SXTw[(i0+2)*16 + tcol] = v2; SXTw[(i0+3)*16 + tcol] = v3;
                }
            }
        }
        __syncwarp();

        // ---- GEMM1: h = x @ W1 + b1  (K=148, plain layout) ----
        u64t ha[8][2];
        bias8(sm + A2_BIAS, wc, ha);
#pragma unroll 1
        for (int kg = 0; kg < 37; kg++) {
#pragma unroll
            for (int kk = 0; kk < 4; kk++) {
                int k = kg*4 + kk;
                gstep(SXTw + k*16 + tb4, sm + A2_W1 + k*CW + wc, ha);
            }
        }

        // ---- LN1 ----
        {
            u64t sp0 = ha[0][0], sp1 = ha[0][1];
#pragma unroll
            for (int f = 1; f < 8; f++) { sp0 = add2(sp0, ha[f][0]); sp1 = add2(sp1, ha[f][1]); }
#pragma unroll
            for (int msk = 1; msk < 8; msk <<= 1) {
                sp0 = add2(sp0, shflx(sp0, msk)); sp1 = add2(sp1, shflx(sp1, msk));
            }
            u64t i64 = dup2(inv64);
            u64t mu0 = mul2(sp0, i64), mu1 = mul2(sp1, i64);
            u64t mn0 = mul2(mu0, dup2(-1.f)), mn1 = mul2(mu1, dup2(-1.f));
            u64t vs0 = 0ull, vs1 = 0ull;
#pragma unroll
            for (int f = 0; f < 8; f++) {
                u64t e0 = add2(ha[f][0], mn0), e1 = add2(ha[f][1], mn1);
                vs0 = ffma2(e0, e0, vs0); vs1 = ffma2(e1, e1, vs1);
            }
#pragma unroll
            for (int msk = 1; msk < 8; msk <<= 1) {
                vs0 = add2(vs0, shflx(vs0, msk)); vs1 = add2(vs1, shflx(vs1, msk));
            }
            float v0, v1, v2, v3;
            up2(vs0, v0, v1); up2(vs1, v2, v3);
            u64t iv0 = pack2(rsqrtf(v0*inv64 + 1e-5f), rsqrtf(v1*inv64 + 1e-5f));
            u64t iv1 = pack2(rsqrtf(v2*inv64 + 1e-5f), rsqrtf(v3*inv64 + 1e-5f));
            u64t gd[8][2], yn[8][2];
            bias8(sm + A2_BIAS + 1*CW, wc, gd);
#pragma unroll
            for (int f = 0; f < 8; f++) {
                yn[f][0] = mul2(mul2(add2(ha[f][0], mn0), iv0), gd[f][0]);
                yn[f][1] = mul2(mul2(add2(ha[f][1], mn1), iv1), gd[f][1]);
            }
            bias8(sm + A2_BIAS + 2*CW, wc, gd);
#pragma unroll
            for (int f = 0; f < 8; f++) {
                yn[f][0] = add2(yn[f][0], gd[f][0]);
                yn[f][1] = add2(yn[f][1], gd[f][1]);
            }
            __syncwarp();
            sts8(ACTw, c, r, yn);
            __syncwarp();
        }

        // ---- k / q : GEMM + |.|^2 + prm_exp ----
#pragma unroll 1
        for (int kq = 0; kq < 2; kq++) {
            u64t ka[8][2];
            bias8(sm + A2_BIAS + (3+kq)*CW, wc, ka);
            gemm64(ACTw, r, sm + A2_WK + kq*(64*CW) + wc, ka);
            // -0.5*|k|^2 per token
            u64t vs0 = 0ull, vs1 = 0ull;
#pragma unroll
            for (int f = 0; f < 8; f++) {
                vs0 = ffma2(ka[f][0], ka[f][0], vs0);
                vs1 = ffma2(ka[f][1], ka[f][1], vs1);
            }
#pragma unroll
            for (int msk = 1; msk < 8; msk <<= 1) {
                vs0 = add2(vs0, shflx(vs0, msk)); vs1 = add2(vs1, shflx(vs1, msk));
            }
            u64t nxd0 = mul2(vs0, dup2(-0.5f)), nxd1 = mul2(vs1, dup2(-0.5f));
            __syncwarp();
            sts8(KACTw, c, r, ka);
            __syncwarp();
            // prm: p[m] = w[:,m] . kvec   (4 cols m=4c..4c+3, 4 tokens)
            u64t pa[4][2];
#pragma unroll
            for (int mm = 0; mm < 4; mm++) { pa[mm][0] = 0ull; pa[mm][1] = 0ull; }
#pragma unroll 1
            for (int kg = 0; kg < 8; kg++) {
                int sw = 4*(r ^ (kg & 3));
#pragma unroll
                for (int kk = 0; kk < 8; kk++) {
                    int k = kg*8 + kk;
                    ulonglong2 av = *(const ulonglong2*)(KACTw + k*16 + sw);
                    float4 w = *(const float4*)(sm + A2_WT + k*36 + 4*c);
#pragma unroll
                    for (int mm = 0; mm < 4; mm++) {
                        u64t wd = dup2(((const float*)&w)[mm]);
                        pa[mm][0] = ffma2(wd, av.x, pa[mm][0]);
                        pa[mm][1] = ffma2(wd, av.y, pa[mm][1]);
                    }
                }
            }
            float pv[4][4];
#pragma unroll
            for (int mm = 0; mm < 4; mm++) {
                float u0, u1, u2, u3;
                up2(add2(pa[mm][0], nxd0), u0, u1);
                up2(add2(pa[mm][1], nxd1), u2, u3);
                pv[mm][0] = __expf(u0)*rsM; pv[mm][1] = __expf(u1)*rsM;
                pv[mm][2] = __expf(u2)*rsM; pv[mm][3] = __expf(u3)*rsM;
            }
            if (kq == 0) {   // kp: [token][32]
#pragma unroll
                for (int tt = 0; tt < 4; tt++)
                    *(float4*)(d_kp + (tok0 + tb4 + tt)*32 + 4*c) =
                        make_float4(pv[0][tt], pv[1][tt], pv[2][tt], pv[3][tt]);
            } else {         // qp: tiled [tile][m][16]
#pragma unroll
                for (int mm = 0; mm < 4; mm++)
                    *(float4*)(d_qp + (long long)tile*512 + (4*c+mm)*16 + tb4) =
                        make_float4(pv[mm][0], pv[mm][1], pv[mm][2], pv[mm][3]);
            }
        }

        // ---- v ----
        {
            u64t va[8][2];
            bias8(sm + A2_BIAS + 5*CW, wc, va);
            gemm64(ACTw, r, sm + A2_WK + 2*(64*CW) + wc, va);
#pragma unroll
            for (int p = 0; p < 2; p++) {
                float lo[8], hi[8];
#pragma unroll
                for (int f = 0; f < 8; f++) up2(va[f][p], lo[f], hi[f]);
                float* o0 = d_v + (tok0 + tb4 + 2*p    )*64 + 8*c;
                float* o1 = d_v + (tok0 + tb4 + 2*p + 1)*64 + 8*c;
                *(float4*)o0     = make_float4(lo[0],lo[1],lo[2],lo[3]);
                *(float4*)(o0+4) = make_float4(lo[4],lo[5],lo[6],lo[7]);
                *(float4*)o1     = make_float4(hi[0],hi[1],hi[2],hi[3]);
                *(float4*)(o1+4) = make_float4(hi[4],hi[5],hi[6],hi[7]);
            }
        }
    }
}

// ===================== zero =====================
__global__ void kernelZero() {
    int i = blockIdx.x*blockDim.x + threadIdx.x;
    if (i < BATCH*MF)     d_kpsum[i] = 0.f;
    if (i < BATCH*DIM*MF) d_kptv[i]  = 0.f;
}

// ===================== Kernel B =====================
#define B_TILE 8
__global__ void __launch_bounds__(256) kernelB()
{
    __shared__ float sv [B_TILE*64];
    __shared__ float skp[B_TILE*32];
    const int tid = threadIdx.x;
    const int b   = blockIdx.y;
    const int m   = tid & 31, dg = tid >> 5;

    float acc[8];
#pragma unroll
    for (int j = 0; j < 8; j++) acc[j] = 0.f;
    float ks = 0.f;

    const int t0 = blockIdx.x * (TSEQ/8);
    const int t1 = t0 + (TSEQ/8);
    for (int base = t0; base < t1; base += B_TILE) {
        __syncthreads();
        {
            const float4* src = (const float4*)(d_v + ((long long)(b*TSEQ + base))*64);
            if (tid < B_TILE*16) ((float4*)sv)[tid] = src[tid];
            const float4* srck = (const float4*)(d_kp + ((long long)(b*TSEQ + base))*32);
            if (tid < B_TILE*8) ((float4*)skp)[tid] = srck[tid];
        }
        __syncthreads();
#pragma unroll
        for (int tt = 0; tt < B_TILE; tt++) {
            float kpm = skp[tt*32 + m];
#pragma unroll
            for (int j = 0; j < 8; j++)
                acc[j] = fmaf(kpm, sv[tt*64 + dg*8 + j], acc[j]);
            if (dg == 0) ks += kpm;
        }
    }
#pragma unroll
    for (int j = 0; j < 8; j++)
        atomicAdd(&d_kptv[b*2048 + (dg*8 + j)*32 + m], acc[j]);
    if (dg == 0) atomicAdd(&d_kpsum[b*32 + m], ks);
}

// ===================== Kernel C (unchanged from R13) =====================
#define C_W2    0
#define C_WM1   4352
#define C_WM2   8704
#define C_KPTV  13056
#define C_KPS2  15232
#define C_B2    15296
#define C_G2    15364
#define C_BE2   15432
#define C_BM1   15500
#define C_BM2   15568
#define C_ACT   15636
#define C_QP    (C_ACT + NW*1024)
#define C_SMEM_BYTES ((C_QP + NW*512)*4)

__global__ void __launch_bounds__(512) kernelC(
    const float* __restrict__ W2,  const float* __restrict__ b2,
    const float* __restrict__ g2,  const float* __restrict__ be2,
    const float* __restrict__ Wm1, const float* __restrict__ bm1,
    const float* __restrict__ Wm2, const float* __restrict__ bm2,
    float* __restrict__ out)
{
    extern __shared__ float sm[];
    const int tid = threadIdx.x, lane = tid & 31, warp = tid >> 5;
    const int b = blockIdx.y;
    const int c = lane & 7, r = lane >> 3;
    const int wc = 8*c + 4*(c >> 2);
    const int tb4 = 4*r;

    for (int idx = tid; idx < 4096; idx += 512) {
        int k = idx >> 6, j = idx & 63;
        int pos = k*CW + j + 4*(j >> 5);
        sm[C_W2  + pos] = W2 [idx];
        sm[C_WM1 + pos] = Wm1[idx];
        sm[C_WM2 + pos] = Wm2[idx];
    }
    for (int idx = tid; idx < 2048; idx += 512) {
        int d = idx >> 5, m = idx & 31;
        sm[C_KPTV + m*CW + d + 4*(d >> 5)] = d_kptv[b*2048 + idx];
    }
    if (tid < 32) {
        float v = d_kpsum[b*32 + tid];
        sm[C_KPS2 + 2*tid] = v; sm[C_KPS2 + 2*tid + 1] = v;
    }
    if (tid < 64) {
        int pos = tid + 4*(tid >> 5);
        sm[C_B2  + pos] = b2 [tid];
        sm[C_G2  + pos] = g2 [tid];
        sm[C_BE2 + pos] = be2[tid];
        sm[C_BM1 + pos] = bm1[tid];
        sm[C_BM2 + pos] = bm2[tid];
    }
    __syncthreads();

    float* ACTw = sm + C_ACT + warp*1024;
    float* QPw  = sm + C_QP  + warp*512;
    const float inv64 = 1.0f/64.0f;
    const long long btile = (long long)b*NTILE;

    for (int tile = blockIdx.x*NW + warp; tile < NTILE; tile += gridDim.x*NW) {
        {
            const float4* qs = (const float4*)(d_qp + (btile + tile)*512);
            float4* qd = (float4*)QPw;
            qd[lane] = qs[lane]; qd[lane+32] = qs[lane+32];
            qd[lane+64] = qs[lane+64]; qd[lane+96] = qs[lane+96];
        }
        __syncwarp();

        u64t acc[8][2];
#pragma unroll
        for (int f = 0; f < 8; f++) { acc[f][0] = 0ull; acc[f][1] = 0ull; }
#pragma unroll 4
        for (int m = 0; m < 32; m++)
            gstep(QPw + m*16 + tb4, sm + C_KPTV + m*CW + wc, acc);
        u64t D0 = 0ull, D1 = 0ull;
#pragma unroll 8
        for (int m = 0; m < 32; m++) {
            ulonglong2 av = *(const ulonglong2*)(QPw + m*16 + tb4);
            u64t kd = *(const u64t*)(sm + C_KPS2 + 2*m);
            D0 = ffma2(av.x, kd, D0); D1 = ffma2(av.y, kd, D1);
        }
        float dd0, dd1, dd2, dd3;
        up2(D0, dd0, dd1); up2(D1, dd2, dd3);
        u64t rp0 = pack2(1.0f/(dd0+1e-8f), 1.0f/(dd1+1e-8f));
        u64t rp1 = pack2(1.0f/(dd2+1e-8f), 1.0f/(dd3+1e-8f));
#pragma unroll
        for (int f = 0; f < 8; f++) {
            acc[f][0] = mul2(acc[f][0], rp0);
            acc[f][1] = mul2(acc[f][1], rp1);
        }
        __syncwarp();
        sts8(ACTw, c, r, acc);
        __syncwarp();

        u64t yy[8][2];
        bias8(sm + C_B2, wc, yy);
        gemm64(ACTw, r, sm + C_W2 + wc, yy);
        {
            const long long tokg = (long long)b*TSEQ + tile*16 + tb4;
            const float* vb = d_v + tokg*64 + 8*c;
#pragma unroll
            for (int p = 0; p < 2; p++) {
                float4 a0 = *(const float4*)(vb + (2*p)*64);
                float4 a1 = *(const float4*)(vb + (2*p)*64 + 4);
                float4 c0 = *(const float4*)(vb + (2*p+1)*64);
                float4 c1 = *(const float4*)(vb + (2*p+1)*64 + 4);
#pragma unroll
                for (int f = 0; f < 4; f++) {
                    yy[f][p]   = add2(yy[f][p],   pack2(((const float*)&a0)[f], ((const float*)&c0)[f]));
                    yy[4+f][p] = add2(yy[4+f][p], pack2(((const float*)&a1)[f], ((const float*)&c1)[f]));
                }
            }
        }

        u64t mu[2], iv[2];
        {
            u64t sp0 = yy[0][0], sp1 = yy[0][1];
#pragma unroll
            for (int f = 1; f < 8; f++) { sp0 = add2(sp0, yy[f][0]); sp1 = add2(sp1, yy[f][1]); }
#pragma unroll
            for (int msk = 1; msk < 8; msk <<= 1) {
                sp0 = add2(sp0, shflx(sp0, msk));
                sp1 = add2(sp1, shflx(sp1, msk));
            }
            u64t i64 = dup2(inv64);
            mu[0] = mul2(sp0, i64); mu[1] = mul2(sp1, i64);
            u64t mn0 = mul2(mu[0], dup2(-1.f)), mn1 = mul2(mu[1], dup2(-1.f));
            u64t vs0 = 0ull, vs1 = 0ull;
#pragma unroll
            for (int f = 0; f < 8; f++) {
                u64t e0 = add2(yy[f][0], mn0), e1 = add2(yy[f][1], mn1);
                vs0 = ffma2(e0, e0, vs0); vs1 = ffma2(e1, e1, vs1);
            }
#pragma unroll
            for (int msk = 1; msk < 8; msk <<= 1) {
                vs0 = add2(vs0, shflx(vs0, msk));
                vs1 = add2(vs1, shflx(vs1, msk));
            }
            float v0, v1, v2, v3;
            up2(vs0, v0, v1); up2(vs1, v2, v3);
            iv[0] = pack2(rsqrtf(v0*inv64 + 1e-5f), rsqrtf(v1*inv64 + 1e-5f));
            iv[1] = pack2(rsqrtf(v2*inv64 + 1e-5f), rsqrtf(v3*inv64 + 1e-5f));
        }
        {
            u64t gd[8][2], yn[8][2];
            bias8(sm + C_G2, wc, gd);
            u64t mn0 = mul2(mu[0], dup2(-1.f)), mn1 = mul2(mu[1], dup2(-1.f));
#pragma unroll
            for (int f = 0; f < 8; f++) {
                yn[f][0] = mul2(mul2(add2(yy[f][0], mn0), iv[0]), gd[f][0]);
                yn[f][1] = mul2(mul2(add2(yy[f][1], mn1), iv[1]), gd[f][1]);
            }
            bias8(sm + C_BE2, wc, gd);
#pragma unroll
            for (int f = 0; f < 8; f++) {
                yn[f][0] = add2(yn[f][0], gd[f][0]);
                yn[f][1] = add2(yn[f][1], gd[f][1]);
            }
            __syncwarp();
            sts8(ACTw, c, r, yn);
            __syncwarp();
        }

        {
            u64t za[8][2];
            bias8(sm + C_BM1, wc, za);
            gemm64(ACTw, r, sm + C_WM1 + wc, za);
#pragma unroll
            for (int f = 0; f < 8; f++) {
#pragma unroll
                for (int p = 0; p < 2; p++) {
                    float u, v; up2(za[f][p], u, v);
                    za[f][p] = pack2(gelu(u), gelu(v));
                }
            }
            __syncwarp();
            sts8(ACTw, c, r, za);
            __syncwarp();
        }

        {
            u64t oa[8][2];
            bias8(sm + C_BM2, wc, oa);
            gemm64(ACTw, r, sm + C_WM2 + wc, oa);
#pragma unroll
            for (int f = 0; f < 8; f++) {
                oa[f][0] = add2(oa[f][0], yy[f][0]);
                oa[f][1] = add2(oa[f][1], yy[f][1]);
            }
            const long long tokg = (long long)b*TSEQ + tile*16 + tb4;
            float* ob = out + tokg*64 + 8*c;
#pragma unroll
            for (int p = 0; p < 2; p++) {
                float lo[8], hi[8];
#pragma unroll
                for (int f = 0; f < 8; f++) up2(oa[f][p], lo[f], hi[f]);
                *(float4*)(ob + (2*p)*64)       = make_float4(lo[0],lo[1],lo[2],lo[3]);
                *(float4*)(ob + (2*p)*64 + 4)   = make_float4(lo[4],lo[5],lo[6],lo[7]);
                *(float4*)(ob + (2*p+1)*64)     = make_float4(hi[0],hi[1],hi[2],hi[3]);
                *(float4*)(ob + (2*p+1)*64 + 4) = make_float4(hi[4],hi[5],hi[6],hi[7]);
            }
        }
        __syncwarp();
    }
}

// ===================== launch =====================
extern "C" void kernel_launch(void* const* d_in, const int* in_sizes, int n_in,
                              void* d_out, int out_size)
{
    const float* x   = (const float*)d_in[0];
    const float* W1  = (const float*)d_in[1];
    const float* b1  = (const float*)d_in[2];
    const float* Wk  = (const float*)d_in[3];
    const float* bk  = (const float*)d_in[4];
    const float* W2  = (const float*)d_in[5];
    const float* b2  = (const float*)d_in[6];
    const float* g1  = (const float*)d_in[7];
    const float* be1 = (const float*)d_in[8];
    const float* g2  = (const float*)d_in[9];
    const float* be2 = (const float*)d_in[10];
    const float* Wm1 = (const float*)d_in[11];
    const float* bm1 = (const float*)d_in[12];
    const float* Wm2 = (const float*)d_in[13];
    const float* bm2 = (const float*)d_in[14];
    const float* wrf = (const float*)d_in[15];
    float* out = (float*)d_out;

    cudaFuncSetAttribute(kernelA, cudaFuncAttributeMaxDynamicSharedMemorySize, A2_SMEM_BYTES);
    cudaFuncSetAttribute(kernelC, cudaFuncAttributeMaxDynamicSharedMemorySize, C_SMEM_BYTES);

    kernelA<<<148, 256, A2_SMEM_BYTES>>>(x, W1, b1, Wk, bk, g1, be1, wrf);
    kernelZero<<<(BATCH*DIM*MF + 255)/256, 256>>>();
    kernelB<<<dim3(8, BATCH), 256>>>();
    kernelC<<<dim3(7, BATCH), 512, C_SMEM_BYTES>>>(W2, b2, g2, be2, Wm1, bm1, Wm2, bm2, out);
}